// round 2
// baseline (speedup 1.0000x reference)
#include <cuda_runtime.h>

// ---------------------------------------------------------------------------
// LowRankBilinearFusion: o[b,m,r,f] = relu( sum_k Wp[f,k]*up[b,m,k]*vp[b,r,k] + bp[f] )
//   up = u @ Wu^T  (B*M=1024 rows, K=1024 -> 256)
//   vp = v @ Wv^T  (B*R=4096 rows, K=2048 -> 256)
// Strategy: per (b,m), fold up[b,m,:] into Wp columns, then 128x256x256 GEMM.
// fp32 with packed fma.rn.f32x2 (Blackwell FFMA2) for 2x fp32 throughput.
// ---------------------------------------------------------------------------

__device__ float g_up[1024 * 256];   // (B*M, 256)
__device__ float g_vp[4096 * 256];   // (B*R, 256)

__device__ __forceinline__ unsigned long long fma2(unsigned long long a,
                                                   unsigned long long b,
                                                   unsigned long long c) {
    unsigned long long d;
    asm("fma.rn.f32x2 %0, %1, %2, %3;" : "=l"(d) : "l"(a), "l"(b), "l"(c));
    return d;
}
__device__ __forceinline__ unsigned long long pack2(float lo, float hi) {
    unsigned long long r;
    asm("mov.b64 %0, {%1, %2};" : "=l"(r) : "f"(lo), "f"(hi));
    return r;
}
__device__ __forceinline__ void unpack2(unsigned long long p, float& lo, float& hi) {
    asm("mov.b64 {%0, %1}, %2;" : "=f"(lo), "=f"(hi) : "l"(p));
}

// ---------------------------------------------------------------------------
// Projection GEMM: C[row, n] = sum_k A[row, k] * W[n, k]     (N = 256 fixed)
// Tiles: 64 rows x 64 cols, BK = 16, 256 threads, 4x4 per thread.
// Row-pairing not needed; col-pairs via direct LDS.128 of W tile.
// ---------------------------------------------------------------------------
template <int KTOT>
__global__ void __launch_bounds__(256) proj_kernel(const float* __restrict__ A,
                                                   const float* __restrict__ W,
                                                   float* __restrict__ C) {
    __shared__ __align__(16) float As[16][68];
    __shared__ __align__(16) float Ws[16][68];

    const int row0 = blockIdx.x * 64;
    const int n0   = blockIdx.y * 64;
    const int t    = threadIdx.x;
    const int ty   = t >> 4;      // 0..15 -> rows ty*4..+4
    const int tx   = t & 15;      // 0..15 -> cols tx*4..+4
    const int lr   = t >> 2;      // 0..63
    const int lk   = (t & 3) * 4; // 0,4,8,12

    const float* Aptr = A + (long)(row0 + lr) * KTOT + lk;
    const float* Wptr = W + (long)(n0 + lr) * KTOT + lk;

    unsigned long long acc[4][2] = {};

    for (int k0 = 0; k0 < KTOT; k0 += 16) {
        float4 av = *(const float4*)(Aptr + k0);
        float4 wv = *(const float4*)(Wptr + k0);
        As[lk + 0][lr] = av.x; As[lk + 1][lr] = av.y;
        As[lk + 2][lr] = av.z; As[lk + 3][lr] = av.w;
        Ws[lk + 0][lr] = wv.x; Ws[lk + 1][lr] = wv.y;
        Ws[lk + 2][lr] = wv.z; Ws[lk + 3][lr] = wv.w;
        __syncthreads();

#pragma unroll
        for (int k = 0; k < 16; k++) {
            float4 bv = *(const float4*)&Ws[k][tx * 4];   // conflict-free LDS.128
            unsigned long long b0 = pack2(bv.x, bv.y);
            unsigned long long b1 = pack2(bv.z, bv.w);
#pragma unroll
            for (int r = 0; r < 4; r++) {
                float a = As[k][ty * 4 + r];              // broadcast LDS
                unsigned long long a2 = pack2(a, a);
                acc[r][0] = fma2(a2, b0, acc[r][0]);
                acc[r][1] = fma2(a2, b1, acc[r][1]);
            }
        }
        __syncthreads();
    }

#pragma unroll
    for (int r = 0; r < 4; r++) {
        float4 o;
        unpack2(acc[r][0], o.x, o.y);
        unpack2(acc[r][1], o.z, o.w);
        *(float4*)&C[(long)(row0 + ty * 4 + r) * 256 + n0 + tx * 4] = o;
    }
}

// ---------------------------------------------------------------------------
// Fused bilinear + p-linear + bias + relu.
// One block per (b*32+m, f-tile of 128). Computes O[128 r x 128 f]:
//   O[r,f] = relu( sum_k vp[b,r,k] * (Wp[f0+f,k] * up[bm,k]) + bp[f0+f] )
// 256 threads, 8 rows x 8 cols per thread (cols split tx*4 and tx*4+64).
// ---------------------------------------------------------------------------
__global__ void __launch_bounds__(256, 2) fuse_kernel(const float* __restrict__ up,
                                                      const float* __restrict__ vp,
                                                      const float* __restrict__ Wp,
                                                      const float* __restrict__ bp,
                                                      float* __restrict__ out) {
    __shared__ __align__(16) float Vs[16][136];
    __shared__ __align__(16) float Ps[16][136];
    __shared__ float ups[256];

    const int bm = blockIdx.x;          // 0..1023
    const int b  = bm >> 5;             // 0..31
    const int f0 = blockIdx.y * 128;    // 0 or 128
    const int t  = threadIdx.x;
    const int ty = t >> 4;              // rows ty*8..+8
    const int tx = t & 15;              // cols tx*4 and tx*4+64
    const int lr = t >> 1;              // 0..127
    const int lk = (t & 1) * 8;         // 0 or 8

    ups[t] = up[(long)bm * 256 + t];
    __syncthreads();

    const float* vbase = vp + ((long)(b * 128 + lr)) * 256;
    const float* wbase = Wp + ((long)(f0 + lr)) * 256;

    unsigned long long acc[8][4] = {};

    for (int kk = 0; kk < 256; kk += 16) {
        float4 v0 = *(const float4*)(vbase + kk + lk);
        float4 v1 = *(const float4*)(vbase + kk + lk + 4);
        float4 w0 = *(const float4*)(wbase + kk + lk);
        float4 w1 = *(const float4*)(wbase + kk + lk + 4);

        Vs[lk + 0][lr] = v0.x; Vs[lk + 1][lr] = v0.y;
        Vs[lk + 2][lr] = v0.z; Vs[lk + 3][lr] = v0.w;
        Vs[lk + 4][lr] = v1.x; Vs[lk + 5][lr] = v1.y;
        Vs[lk + 6][lr] = v1.z; Vs[lk + 7][lr] = v1.w;

        Ps[lk + 0][lr] = w0.x * ups[kk + lk + 0];
        Ps[lk + 1][lr] = w0.y * ups[kk + lk + 1];
        Ps[lk + 2][lr] = w0.z * ups[kk + lk + 2];
        Ps[lk + 3][lr] = w0.w * ups[kk + lk + 3];
        Ps[lk + 4][lr] = w1.x * ups[kk + lk + 4];
        Ps[lk + 5][lr] = w1.y * ups[kk + lk + 5];
        Ps[lk + 6][lr] = w1.z * ups[kk + lk + 6];
        Ps[lk + 7][lr] = w1.w * ups[kk + lk + 7];
        __syncthreads();

#pragma unroll
        for (int k = 0; k < 16; k++) {
            float4 bA = *(const float4*)&Ps[k][tx * 4];        // conflict-free
            float4 bB = *(const float4*)&Ps[k][tx * 4 + 64];   // conflict-free
            unsigned long long b0 = pack2(bA.x, bA.y);
            unsigned long long b1 = pack2(bA.z, bA.w);
            unsigned long long b2 = pack2(bB.x, bB.y);
            unsigned long long b3 = pack2(bB.z, bB.w);
#pragma unroll
            for (int r = 0; r < 8; r++) {
                float a = Vs[k][ty * 8 + r];                   // broadcast LDS
                unsigned long long a2 = pack2(a, a);
                acc[r][0] = fma2(a2, b0, acc[r][0]);
                acc[r][1] = fma2(a2, b1, acc[r][1]);
                acc[r][2] = fma2(a2, b2, acc[r][2]);
                acc[r][3] = fma2(a2, b3, acc[r][3]);
            }
        }
        __syncthreads();
    }

    // epilogue: + bias, relu, vectorized store
    float4 biasA = *(const float4*)&bp[f0 + tx * 4];
    float4 biasB = *(const float4*)&bp[f0 + tx * 4 + 64];

#pragma unroll
    for (int r = 0; r < 8; r++) {
        int row = ty * 8 + r;
        float4 oA, oB;
        unpack2(acc[r][0], oA.x, oA.y);
        unpack2(acc[r][1], oA.z, oA.w);
        unpack2(acc[r][2], oB.x, oB.y);
        unpack2(acc[r][3], oB.z, oB.w);
        oA.x = fmaxf(oA.x + biasA.x, 0.f);
        oA.y = fmaxf(oA.y + biasA.y, 0.f);
        oA.z = fmaxf(oA.z + biasA.z, 0.f);
        oA.w = fmaxf(oA.w + biasA.w, 0.f);
        oB.x = fmaxf(oB.x + biasB.x, 0.f);
        oB.y = fmaxf(oB.y + biasB.y, 0.f);
        oB.z = fmaxf(oB.z + biasB.z, 0.f);
        oB.w = fmaxf(oB.w + biasB.w, 0.f);
        long obase = (long)bm * 128 * 256 + (long)row * 256 + f0;
        *(float4*)&out[obase + tx * 4]      = oA;
        *(float4*)&out[obase + tx * 4 + 64] = oB;
    }
}

extern "C" void kernel_launch(void* const* d_in, const int* in_sizes, int n_in,
                              void* d_out, int out_size) {
    const float* u  = (const float*)d_in[0];   // (32,32,1024)
    const float* v  = (const float*)d_in[1];   // (32,128,2048)
    const float* Wu = (const float*)d_in[2];   // (256,1024)
    const float* Wv = (const float*)d_in[3];   // (256,2048)
    const float* Wp = (const float*)d_in[4];   // (256,256)
    const float* bp = (const float*)d_in[5];   // (256,)
    float* out = (float*)d_out;                // (32,32,128,256)

    float* up_ptr = nullptr;
    float* vp_ptr = nullptr;
    cudaGetSymbolAddress((void**)&up_ptr, g_up);
    cudaGetSymbolAddress((void**)&vp_ptr, g_vp);

    // up = u @ Wu^T : 1024 rows, K=1024
    proj_kernel<1024><<<dim3(16, 4), 256>>>(u, Wu, up_ptr);
    // vp = v @ Wv^T : 4096 rows, K=2048
    proj_kernel<2048><<<dim3(64, 4), 256>>>(v, Wv, vp_ptr);
    // fused bilinear + p-linear + relu
    fuse_kernel<<<dim3(1024, 2), 256>>>(up_ptr, vp_ptr, Wp, bp, out);
}

// round 5
// speedup vs baseline: 1.8959x; 1.8959x over previous
#include <cuda_runtime.h>
#include <cuda_bf16.h>
#include <cuda_fp16.h>
#include <cstdint>

// ============================================================================
// LowRankBilinearFusion via mma.sync (sm_80-class PTX -> HMMA tensor pipe).
//   up = u @ Wu^T      (1024 x 256, K=1024)      bf16x3 error-free split
//   vp = v @ Wv^T      (4096 x 256, K=2048)      bf16x3, K-split x2 + add
//   out[bm] = relu((vp[b] ⊙ up[bm]) @ Wp^T + bp) per bm: 128 x 256, K=256
//                                                fp16 A + fp16 (Bh+Bl): 2 products
// ============================================================================

// -------------------- device scratch (no cudaMalloc allowed) ----------------
__device__ float g_up[1024 * 256];
__device__ float g_vp[4096 * 256];
__device__ float g_vp_part[2 * 4096 * 256];
__device__ __nv_bfloat16 g_wuh[256 * 1024], g_wul[256 * 1024];
__device__ __nv_bfloat16 g_wvh[256 * 2048], g_wvl[256 * 2048];
__device__ __half g_wph[256 * 256], g_wpl[256 * 256];

#define SWZ(o) ((o) ^ (((o) >> 3) & 0x70))

__device__ __forceinline__ uint32_t smem_u32(const void* p) {
    uint32_t a;
    asm("{ .reg .u64 t; cvta.to.shared.u64 t, %1; cvt.u32.u64 %0, t; }" : "=r"(a) : "l"(p));
    return a;
}
__device__ __forceinline__ void ldsm4(uint32_t& r0, uint32_t& r1, uint32_t& r2, uint32_t& r3,
                                      uint32_t addr) {
    asm volatile("ldmatrix.sync.aligned.m8n8.x4.shared.b16 {%0,%1,%2,%3}, [%4];"
                 : "=r"(r0), "=r"(r1), "=r"(r2), "=r"(r3) : "r"(addr));
}
__device__ __forceinline__ void mma_bf16(float* c, const uint32_t* a, const uint32_t* b) {
    asm volatile(
        "mma.sync.aligned.m16n8k16.row.col.f32.bf16.bf16.f32 "
        "{%0,%1,%2,%3}, {%4,%5,%6,%7}, {%8,%9}, {%0,%1,%2,%3};"
        : "+f"(c[0]), "+f"(c[1]), "+f"(c[2]), "+f"(c[3])
        : "r"(a[0]), "r"(a[1]), "r"(a[2]), "r"(a[3]), "r"(b[0]), "r"(b[1]));
}
__device__ __forceinline__ void mma_f16(float* c, const uint32_t* a, const uint32_t* b) {
    asm volatile(
        "mma.sync.aligned.m16n8k16.row.col.f32.f16.f16.f32 "
        "{%0,%1,%2,%3}, {%4,%5,%6,%7}, {%8,%9}, {%0,%1,%2,%3};"
        : "+f"(c[0]), "+f"(c[1]), "+f"(c[2]), "+f"(c[3])
        : "r"(a[0]), "r"(a[1]), "r"(a[2]), "r"(a[3]), "r"(b[0]), "r"(b[1]));
}

// -------------------- prep: split weights -----------------------------------
__global__ void __launch_bounds__(256) prep_split(
    const float* __restrict__ Wu, const float* __restrict__ Wv, const float* __restrict__ Wp,
    __nv_bfloat16* wuh, __nv_bfloat16* wul,
    __nv_bfloat16* wvh, __nv_bfloat16* wvl,
    __half* wph, __half* wpl) {
    const int NU = 256 * 1024, NV = 256 * 2048, NP = 256 * 256;
    int i = blockIdx.x * 256 + threadIdx.x;
    if (i < NU) {
        float x = Wu[i];
        __nv_bfloat16 h = __float2bfloat16(x);
        wuh[i] = h; wul[i] = __float2bfloat16(x - __bfloat162float(h));
    } else if (i < NU + NV) {
        int j = i - NU;
        float x = Wv[j];
        __nv_bfloat16 h = __float2bfloat16(x);
        wvh[j] = h; wvl[j] = __float2bfloat16(x - __bfloat162float(h));
    } else if (i < NU + NV + NP) {
        int j = i - NU - NV;
        float x = Wp[j];
        __half h = __float2half_rn(x);
        wph[j] = h; wpl[j] = __float2half_rn(x - __half2float(h));
    }
}

// ============================================================================
// proj: C[128 x 128] = sum_k A[row,k] * B[n,k], bf16x3. K-loop = 1024 always.
// Grid: 0..15 -> up (mt 0..7 x n0 0..1), 16..143 -> vp (mt x n0 x kh)
// ============================================================================
__global__ void __launch_bounds__(256) proj_mma(
    const float* __restrict__ u, const float* __restrict__ v,
    const __nv_bfloat16* __restrict__ wuh, const __nv_bfloat16* __restrict__ wul,
    const __nv_bfloat16* __restrict__ wvh, const __nv_bfloat16* __restrict__ wvl,
    float* __restrict__ up, float* __restrict__ vp_part)
{
    extern __shared__ char dsm[];
    uint32_t sb_raw = smem_u32(dsm);
    uint32_t sb = (sb_raw + 1023u) & ~1023u;
    char* smp = dsm + (sb - sb_raw);

    constexpr uint32_t OFF_AH = 0, OFF_AL = 16384, OFF_BH = 32768, OFF_BL = 49152;

    const int bid = blockIdx.x;
    const int tid = threadIdx.x;
    const int wid = tid >> 5, lane = tid & 31;
    const int wm = (wid >> 2) * 64, wn = (wid & 3) * 32;

    const float* A; const __nv_bfloat16 *Bh, *Bl; float* C;
    int lda, ldb;
    if (bid < 16) {
        int mt = bid >> 1, n0 = bid & 1;
        A = u + (size_t)mt * 128 * 1024; lda = 1024;
        Bh = wuh + (size_t)n0 * 128 * 1024; Bl = wul + (size_t)n0 * 128 * 1024; ldb = 1024;
        C = up + (size_t)mt * 128 * 256 + n0 * 128;
    } else {
        int b2 = bid - 16;
        int mt = b2 >> 2, n0 = (b2 >> 1) & 1, kh = b2 & 1;
        A = v + (size_t)mt * 128 * 2048 + kh * 1024; lda = 2048;
        Bh = wvh + (size_t)n0 * 128 * 2048 + kh * 1024;
        Bl = wvl + (size_t)n0 * 128 * 2048 + kh * 1024; ldb = 2048;
        C = vp_part + (size_t)kh * 4096 * 256 + (size_t)mt * 128 * 256 + n0 * 128;
    }

    const int arow = tid >> 1, ahalf = tid & 1;
    const int brow = tid & 127;
    const __nv_bfloat16* bsrc = (tid & 128) ? Bl : Bh;
    const uint32_t boff = (tid & 128) ? OFF_BL : OFF_BH;

    float c[4][4][4];
#pragma unroll
    for (int i = 0; i < 4; i++)
#pragma unroll
        for (int j = 0; j < 4; j++)
#pragma unroll
            for (int q = 0; q < 4; q++) c[i][j][q] = 0.f;

    for (int kc = 0; kc < 16; kc++) {
        // ---- A: fp32 -> bf16 hi/lo -> swizzled smem ----
        {
            const float* ap = A + (size_t)arow * lda + kc * 64 + ahalf * 32;
            const uint32_t rowoff = arow * 128 + ahalf * 64;
#pragma unroll
            for (int i = 0; i < 8; i++) {
                float4 x = *(const float4*)(ap + i * 4);
                __nv_bfloat16 h0 = __float2bfloat16(x.x), h1 = __float2bfloat16(x.y);
                __nv_bfloat16 h2 = __float2bfloat16(x.z), h3 = __float2bfloat16(x.w);
                __nv_bfloat16 l0 = __float2bfloat16(x.x - __bfloat162float(h0));
                __nv_bfloat16 l1 = __float2bfloat16(x.y - __bfloat162float(h1));
                __nv_bfloat16 l2 = __float2bfloat16(x.z - __bfloat162float(h2));
                __nv_bfloat16 l3 = __float2bfloat16(x.w - __bfloat162float(h3));
                uint2 hp, lp;
                hp.x = (uint32_t)__bfloat16_as_ushort(h0) | ((uint32_t)__bfloat16_as_ushort(h1) << 16);
                hp.y = (uint32_t)__bfloat16_as_ushort(h2) | ((uint32_t)__bfloat16_as_ushort(h3) << 16);
                lp.x = (uint32_t)__bfloat16_as_ushort(l0) | ((uint32_t)__bfloat16_as_ushort(l1) << 16);
                lp.y = (uint32_t)__bfloat16_as_ushort(l2) | ((uint32_t)__bfloat16_as_ushort(l3) << 16);
                uint32_t sw = SWZ(rowoff + i * 8);
                *(uint2*)(smp + OFF_AH + sw) = hp;
                *(uint2*)(smp + OFF_AL + sw) = lp;
            }
        }
        // ---- B: copy pre-split bf16 (half threads hi, half lo) ----
        {
            const __nv_bfloat16* bpp = bsrc + (size_t)brow * ldb + kc * 64;
#pragma unroll
            for (int j = 0; j < 8; j++) {
                uint32_t sw = SWZ((uint32_t)(brow * 128 + j * 16));
                *(uint4*)(smp + boff + sw) = *(const uint4*)(bpp + j * 8);
            }
        }
        __syncthreads();

#pragma unroll
        for (int ks = 0; ks < 4; ks++) {
            uint32_t ah[4][4], al[4][4], bh[4][2], bl[4][2];
            const uint32_t acol = (uint32_t)(ks * 32 + (lane >> 4) * 16);
#pragma unroll
            for (int mi = 0; mi < 4; mi++) {
                uint32_t ro = (uint32_t)((wm + mi * 16 + (lane & 15)) * 128) + acol;
                ldsm4(ah[mi][0], ah[mi][1], ah[mi][2], ah[mi][3], sb + OFF_AH + SWZ(ro));
                ldsm4(al[mi][0], al[mi][1], al[mi][2], al[mi][3], sb + OFF_AL + SWZ(ro));
            }
#pragma unroll
            for (int np = 0; np < 2; np++) {
                uint32_t ro = (uint32_t)((wn + np * 16 + (lane & 15)) * 128) + acol;
                uint32_t m0, m1, m2, m3;
                ldsm4(m0, m1, m2, m3, sb + OFF_BH + SWZ(ro));
                bh[2 * np][0] = m0; bh[2 * np][1] = m2;
                bh[2 * np + 1][0] = m1; bh[2 * np + 1][1] = m3;
                ldsm4(m0, m1, m2, m3, sb + OFF_BL + SWZ(ro));
                bl[2 * np][0] = m0; bl[2 * np][1] = m2;
                bl[2 * np + 1][0] = m1; bl[2 * np + 1][1] = m3;
            }
#pragma unroll
            for (int mi = 0; mi < 4; mi++)
#pragma unroll
                for (int nj = 0; nj < 4; nj++) {
                    mma_bf16(c[mi][nj], ah[mi], bh[nj]);
                    mma_bf16(c[mi][nj], al[mi], bh[nj]);
                    mma_bf16(c[mi][nj], ah[mi], bl[nj]);
                }
        }
        __syncthreads();
    }

    const int rin = lane >> 2, cin = (lane & 3) * 2;
#pragma unroll
    for (int mi = 0; mi < 4; mi++)
#pragma unroll
        for (int nj = 0; nj < 4; nj++) {
            float* p0 = C + (size_t)(wm + mi * 16 + rin) * 256 + wn + nj * 8 + cin;
            *(float2*)p0 = make_float2(c[mi][nj][0], c[mi][nj][1]);
            *(float2*)(p0 + 8 * 256) = make_float2(c[mi][nj][2], c[mi][nj][3]);
        }
}

// -------------------- vp = part0 + part1 ------------------------------------
__global__ void __launch_bounds__(256) vp_add(const float* __restrict__ part,
                                              float* __restrict__ vpo) {
    size_t i = ((size_t)blockIdx.x * 256 + threadIdx.x) * 4;
    float4 a = *(const float4*)(part + i);
    float4 b = *(const float4*)(part + (size_t)4096 * 256 + i);
    a.x += b.x; a.y += b.y; a.z += b.z; a.w += b.w;
    *(float4*)(vpo + i) = a;
}

// ============================================================================
// fuse: out[bm] = relu((vp[b] ⊙ up[bm]) @ Wp^T + bp)   128 x 256, K=256
// fp16 A (single) x fp16 B (hi + lo) = 2 products, fp32 accum.
// ============================================================================
__global__ void __launch_bounds__(256) fuse_mma(
    const float* __restrict__ up, const float* __restrict__ vp,
    const __half* __restrict__ wph, const __half* __restrict__ wpl,
    const float* __restrict__ bp, float* __restrict__ out)
{
    extern __shared__ char dsm[];
    uint32_t sb_raw = smem_u32(dsm);
    uint32_t sb = (sb_raw + 1023u) & ~1023u;
    char* smp = dsm + (sb - sb_raw);

    constexpr uint32_t OFF_A = 0, OFF_BH = 16384, OFF_BL = 49152, OFF_MUL = 81920;

    const int bm = blockIdx.x, b = bm >> 5;
    const int tid = threadIdx.x;
    const int wid = tid >> 5, lane = tid & 31;
    const int wm = (wid >> 2) * 64, wn = (wid & 3) * 64;

    float* muls = (float*)(smp + OFF_MUL);
    muls[tid] = up[(size_t)bm * 256 + tid];
    __syncthreads();

    float c[4][8][4];
#pragma unroll
    for (int i = 0; i < 4; i++)
#pragma unroll
        for (int j = 0; j < 8; j++)
#pragma unroll
            for (int q = 0; q < 4; q++) c[i][j][q] = 0.f;

    const int arow = tid >> 1, ahalf = tid & 1;
    const float* vbase = vp + (size_t)(b * 128 + arow) * 256;

    for (int kc = 0; kc < 4; kc++) {
        // ---- A: vp ⊙ up -> fp16 -> swizzled smem ----
        {
            const float* ap = vbase + kc * 64 + ahalf * 32;
            const float* mp = muls + kc * 64 + ahalf * 32;
            const uint32_t rowoff = arow * 128 + ahalf * 64;
#pragma unroll
            for (int i = 0; i < 8; i++) {
                float4 x = *(const float4*)(ap + i * 4);
                const float4 m = *(const float4*)(mp + i * 4);
                x.x *= m.x; x.y *= m.y; x.z *= m.z; x.w *= m.w;
                __half h0 = __float2half_rn(x.x), h1 = __float2half_rn(x.y);
                __half h2 = __float2half_rn(x.z), h3 = __float2half_rn(x.w);
                uint2 hp;
                hp.x = (uint32_t)__half_as_ushort(h0) | ((uint32_t)__half_as_ushort(h1) << 16);
                hp.y = (uint32_t)__half_as_ushort(h2) | ((uint32_t)__half_as_ushort(h3) << 16);
                *(uint2*)(smp + OFF_A + SWZ(rowoff + i * 8)) = hp;
            }
        }
        // ---- B: copy pre-split fp16 Wp (256 rows, hi and lo) ----
        {
            const __half* bhp = wph + (size_t)tid * 256 + kc * 64;
            const __half* blp = wpl + (size_t)tid * 256 + kc * 64;
#pragma unroll
            for (int j = 0; j < 8; j++) {
                uint32_t sw = SWZ((uint32_t)(tid * 128 + j * 16));
                *(uint4*)(smp + OFF_BH + sw) = *(const uint4*)(bhp + j * 8);
                *(uint4*)(smp + OFF_BL + sw) = *(const uint4*)(blp + j * 8);
            }
        }
        __syncthreads();

#pragma unroll
        for (int ks = 0; ks < 4; ks++) {
            uint32_t af[4][4], bf[8][2];
            const uint32_t acol = (uint32_t)(ks * 32 + (lane >> 4) * 16);
#pragma unroll
            for (int mi = 0; mi < 4; mi++) {
                uint32_t ro = (uint32_t)((wm + mi * 16 + (lane & 15)) * 128) + acol;
                ldsm4(af[mi][0], af[mi][1], af[mi][2], af[mi][3], sb + OFF_A + SWZ(ro));
            }
            // product 1: A x Bh
#pragma unroll
            for (int np = 0; np < 4; np++) {
                uint32_t ro = (uint32_t)((wn + np * 16 + (lane & 15)) * 128) + acol;
                uint32_t m0, m1, m2, m3;
                ldsm4(m0, m1, m2, m3, sb + OFF_BH + SWZ(ro));
                bf[2 * np][0] = m0; bf[2 * np][1] = m2;
                bf[2 * np + 1][0] = m1; bf[2 * np + 1][1] = m3;
            }
#pragma unroll
            for (int mi = 0; mi < 4; mi++)
#pragma unroll
                for (int nj = 0; nj < 8; nj++) mma_f16(c[mi][nj], af[mi], bf[nj]);
            // product 2: A x Bl (reuse bf regs)
#pragma unroll
            for (int np = 0; np < 4; np++) {
                uint32_t ro = (uint32_t)((wn + np * 16 + (lane & 15)) * 128) + acol;
                uint32_t m0, m1, m2, m3;
                ldsm4(m0, m1, m2, m3, sb + OFF_BL + SWZ(ro));
                bf[2 * np][0] = m0; bf[2 * np][1] = m2;
                bf[2 * np + 1][0] = m1; bf[2 * np + 1][1] = m3;
            }
#pragma unroll
            for (int mi = 0; mi < 4; mi++)
#pragma unroll
                for (int nj = 0; nj < 8; nj++) mma_f16(c[mi][nj], af[mi], bf[nj]);
        }
        __syncthreads();
    }

    // ---- epilogue: +bias, relu, store ----
    const int rin = lane >> 2, cin = (lane & 3) * 2;
    float* obase = out + (size_t)bm * 128 * 256;
#pragma unroll
    for (int nj = 0; nj < 8; nj++) {
        const int f = wn + nj * 8 + cin;
        const float b0 = bp[f], b1 = bp[f + 1];
#pragma unroll
        for (int mi = 0; mi < 4; mi++) {
            float* p0 = obase + (size_t)(wm + mi * 16 + rin) * 256 + f;
            *(float2*)p0 = make_float2(fmaxf(c[mi][nj][0] + b0, 0.f),
                                       fmaxf(c[mi][nj][1] + b1, 0.f));
            *(float2*)(p0 + 8 * 256) = make_float2(fmaxf(c[mi][nj][2] + b0, 0.f),
                                                   fmaxf(c[mi][nj][3] + b1, 0.f));
        }
    }
}

// -------------------- host launch -------------------------------------------
extern "C" void kernel_launch(void* const* d_in, const int* in_sizes, int n_in,
                              void* d_out, int out_size) {
    const float* u  = (const float*)d_in[0];   // (32,32,1024)
    const float* v  = (const float*)d_in[1];   // (32,128,2048)
    const float* Wu = (const float*)d_in[2];   // (256,1024)
    const float* Wv = (const float*)d_in[3];   // (256,2048)
    const float* Wp = (const float*)d_in[4];   // (256,256)
    const float* bp = (const float*)d_in[5];   // (256,)
    float* out = (float*)d_out;                // (32,32,128,256)

    float *up_p, *vp_p, *vpp_p;
    __nv_bfloat16 *wuh, *wul, *wvh, *wvl;
    __half *wph, *wpl;
    cudaGetSymbolAddress((void**)&up_p, g_up);
    cudaGetSymbolAddress((void**)&vp_p, g_vp);
    cudaGetSymbolAddress((void**)&vpp_p, g_vp_part);
    cudaGetSymbolAddress((void**)&wuh, g_wuh);
    cudaGetSymbolAddress((void**)&wul, g_wul);
    cudaGetSymbolAddress((void**)&wvh, g_wvh);
    cudaGetSymbolAddress((void**)&wvl, g_wvl);
    cudaGetSymbolAddress((void**)&wph, g_wph);
    cudaGetSymbolAddress((void**)&wpl, g_wpl);

    const int PROJ_SMEM = 65536 + 1024;
    const int FUSE_SMEM = 82944 + 1024;
    cudaFuncSetAttribute(proj_mma, cudaFuncAttributeMaxDynamicSharedMemorySize, PROJ_SMEM);
    cudaFuncSetAttribute(fuse_mma, cudaFuncAttributeMaxDynamicSharedMemorySize, FUSE_SMEM);

    const int total = 256 * 1024 + 256 * 2048 + 256 * 256;
    prep_split<<<(total + 255) / 256, 256>>>(Wu, Wv, Wp, wuh, wul, wvh, wvl, wph, wpl);
    proj_mma<<<144, 256, PROJ_SMEM>>>(u, v, wuh, wul, wvh, wvl, up_p, vpp_p);
    vp_add<<<1024, 256>>>(vpp_p, vp_p);
    fuse_mma<<<1024, 256, FUSE_SMEM>>>(up_p, vp_p, wph, wpl, bp, out);
}

// round 6
// speedup vs baseline: 2.7517x; 1.4514x over previous
#include <cuda_runtime.h>
#include <cuda_fp16.h>
#include <cstdint>

// ============================================================================
// LowRankBilinearFusion via mma.sync fp16 (HMMA), precision-budgeted:
//   proj: C = A @ W^T with A = Ah+Al (fp16 error-free split), W fp16  (2 prod)
//   fuse: out[bm] = relu((vp[b] ⊙ up[bm]) @ Wp16^T + bp)              (1 prod)
// Software-pipelined: LDG(next) -> MMA(cur) -> cvt+STS(next) -> sync.
// ============================================================================

__device__ float g_up[1024 * 256];
__device__ float g_vp[4096 * 256];
__device__ float g_vp_part[2 * 4096 * 256];
__device__ __half g_wu16[256 * 1024];
__device__ __half g_wv16[256 * 2048];
__device__ __half g_wp16[256 * 256];

#define SWZ(o) ((o) ^ (((o) >> 3) & 0x70))

__device__ __forceinline__ uint32_t smem_u32(const void* p) {
    uint32_t a;
    asm("{ .reg .u64 t; cvta.to.shared.u64 t, %1; cvt.u32.u64 %0, t; }" : "=r"(a) : "l"(p));
    return a;
}
__device__ __forceinline__ void ldsm4(uint32_t& r0, uint32_t& r1, uint32_t& r2, uint32_t& r3,
                                      uint32_t addr) {
    asm volatile("ldmatrix.sync.aligned.m8n8.x4.shared.b16 {%0,%1,%2,%3}, [%4];"
                 : "=r"(r0), "=r"(r1), "=r"(r2), "=r"(r3) : "r"(addr));
}
__device__ __forceinline__ void mma_f16(float* c, const uint32_t* a, const uint32_t* b) {
    asm volatile(
        "mma.sync.aligned.m16n8k16.row.col.f32.f16.f16.f32 "
        "{%0,%1,%2,%3}, {%4,%5,%6,%7}, {%8,%9}, {%0,%1,%2,%3};"
        : "+f"(c[0]), "+f"(c[1]), "+f"(c[2]), "+f"(c[3])
        : "r"(a[0]), "r"(a[1]), "r"(a[2]), "r"(a[3]), "r"(b[0]), "r"(b[1]));
}
__device__ __forceinline__ uint32_t packh(__half a, __half b) {
    return (uint32_t)__half_as_ushort(a) | ((uint32_t)__half_as_ushort(b) << 16);
}

// -------------------- prep: weights -> fp16 ----------------------------------
__global__ void __launch_bounds__(256) prep_cvt(
    const float* __restrict__ Wu, const float* __restrict__ Wv, const float* __restrict__ Wp,
    __half* wu, __half* wv, __half* wp) {
    const int NU = 256 * 1024, NV = 256 * 2048, NP = 256 * 256;
    int i = blockIdx.x * 256 + threadIdx.x;
    if (i < NU) wu[i] = __float2half_rn(Wu[i]);
    else if (i < NU + NV) wv[i - NU] = __float2half_rn(Wv[i - NU]);
    else if (i < NU + NV + NP) wp[i - NU - NV] = __float2half_rn(Wp[i - NU - NV]);
}

// ============================================================================
// proj: C[128 x 128] = (Ah + Al) @ B16^T, K-loop = 1024 (16 chunks of 64).
// Grid: 0..15 -> up (mt x n0), 16..143 -> vp (mt x n0 x kh), K-split + add.
// smem per buffer: AH 16K | AL 16K | BH 16K  (x2 buffers = 96KB)
// ============================================================================
__global__ void __launch_bounds__(256) proj_mma(
    const float* __restrict__ u, const float* __restrict__ v,
    const __half* __restrict__ wu, const __half* __restrict__ wv,
    float* __restrict__ up, float* __restrict__ vp_part)
{
    extern __shared__ char dsm[];
    uint32_t sb_raw = smem_u32(dsm);
    uint32_t sb = (sb_raw + 1023u) & ~1023u;
    char* smp = dsm + (sb - sb_raw);

    constexpr uint32_t BUF = 49152, OFF_AL = 16384, OFF_BH = 32768;

    const int bid = blockIdx.x;
    const int tid = threadIdx.x;
    const int wid = tid >> 5, lane = tid & 31;
    const int wm = (wid >> 2) * 64, wn = (wid & 3) * 32;

    const float* A; const __half* B; float* C;
    int lda, ldb;
    if (bid < 16) {
        int mt = bid >> 1, n0 = bid & 1;
        A = u + (size_t)mt * 128 * 1024; lda = 1024;
        B = wu + (size_t)n0 * 128 * 1024; ldb = 1024;
        C = up + (size_t)mt * 128 * 256 + n0 * 128;
    } else {
        int b2 = bid - 16;
        int mt = b2 >> 2, n0 = (b2 >> 1) & 1, kh = b2 & 1;
        A = v + (size_t)mt * 128 * 2048 + kh * 1024; lda = 2048;
        B = wv + (size_t)n0 * 128 * 2048 + kh * 1024; ldb = 2048;
        C = vp_part + (size_t)kh * 4096 * 256 + (size_t)mt * 128 * 256 + n0 * 128;
    }

    const int arow = tid >> 1, ahalf = tid & 1;
    const uint32_t arowoff = (uint32_t)(arow * 128 + ahalf * 64);
    const float* abase = A + (size_t)arow * lda + ahalf * 32;
    const int brow = tid >> 1, bhalf = tid & 1;
    const __half* bbase = B + (size_t)brow * ldb + bhalf * 32;
    const uint32_t browoff = (uint32_t)(brow * 128 + bhalf * 64);

    float c[4][4][4];
#pragma unroll
    for (int i = 0; i < 4; i++)
#pragma unroll
        for (int j = 0; j < 4; j++)
#pragma unroll
            for (int q = 0; q < 4; q++) c[i][j][q] = 0.f;

    float4 xa[8];
    uint4 xb[4];

    auto loadA = [&](int kc) {
#pragma unroll
        for (int i = 0; i < 8; i++) xa[i] = *(const float4*)(abase + kc * 64 + i * 4);
    };
    auto loadB = [&](int kc) {
#pragma unroll
        for (int j = 0; j < 4; j++) xb[j] = *(const uint4*)(bbase + kc * 64 + j * 8);
    };
    auto storeAB = [&](int bf) {
        char* p = smp + bf * BUF;
#pragma unroll
        for (int i = 0; i < 8; i++) {
            __half h0 = __float2half_rn(xa[i].x), h1 = __float2half_rn(xa[i].y);
            __half h2 = __float2half_rn(xa[i].z), h3 = __float2half_rn(xa[i].w);
            __half l0 = __float2half_rn(xa[i].x - __half2float(h0));
            __half l1 = __float2half_rn(xa[i].y - __half2float(h1));
            __half l2 = __float2half_rn(xa[i].z - __half2float(h2));
            __half l3 = __float2half_rn(xa[i].w - __half2float(h3));
            uint32_t sw = SWZ(arowoff + i * 8);
            *(uint2*)(p + sw) = make_uint2(packh(h0, h1), packh(h2, h3));
            *(uint2*)(p + OFF_AL + sw) = make_uint2(packh(l0, l1), packh(l2, l3));
        }
#pragma unroll
        for (int j = 0; j < 4; j++)
            *(uint4*)(p + OFF_BH + SWZ(browoff + j * 16)) = xb[j];
    };
    auto mmas = [&](int bf) {
        uint32_t base = sb + bf * BUF;
#pragma unroll
        for (int ks = 0; ks < 4; ks++) {
            uint32_t ah[4][4], al[4][4], bh[4][2];
            const uint32_t acol = (uint32_t)(ks * 32 + (lane >> 4) * 16);
#pragma unroll
            for (int mi = 0; mi < 4; mi++) {
                uint32_t ro = (uint32_t)((wm + mi * 16 + (lane & 15)) * 128) + acol;
                ldsm4(ah[mi][0], ah[mi][1], ah[mi][2], ah[mi][3], base + SWZ(ro));
                ldsm4(al[mi][0], al[mi][1], al[mi][2], al[mi][3], base + OFF_AL + SWZ(ro));
            }
#pragma unroll
            for (int np = 0; np < 2; np++) {
                uint32_t ro = (uint32_t)((wn + np * 16 + (lane & 15)) * 128) + acol;
                uint32_t m0, m1, m2, m3;
                ldsm4(m0, m1, m2, m3, base + OFF_BH + SWZ(ro));
                bh[2 * np][0] = m0; bh[2 * np][1] = m2;
                bh[2 * np + 1][0] = m1; bh[2 * np + 1][1] = m3;
            }
#pragma unroll
            for (int mi = 0; mi < 4; mi++)
#pragma unroll
                for (int nj = 0; nj < 4; nj++) {
                    mma_f16(c[mi][nj], ah[mi], bh[nj]);
                    mma_f16(c[mi][nj], al[mi], bh[nj]);
                }
        }
    };

    loadA(0); loadB(0);
    storeAB(0);
    __syncthreads();
    for (int kc = 0; kc < 16; kc++) {
        if (kc < 15) { loadA(kc + 1); loadB(kc + 1); }
        mmas(kc & 1);
        if (kc < 15) storeAB((kc + 1) & 1);
        __syncthreads();
    }

    const int rin = lane >> 2, cin = (lane & 3) * 2;
#pragma unroll
    for (int mi = 0; mi < 4; mi++)
#pragma unroll
        for (int nj = 0; nj < 4; nj++) {
            float* p0 = C + (size_t)(wm + mi * 16 + rin) * 256 + wn + nj * 8 + cin;
            *(float2*)p0 = make_float2(c[mi][nj][0], c[mi][nj][1]);
            *(float2*)(p0 + 8 * 256) = make_float2(c[mi][nj][2], c[mi][nj][3]);
        }
}

// -------------------- vp = part0 + part1 ------------------------------------
__global__ void __launch_bounds__(256) vp_add(const float* __restrict__ part,
                                              float* __restrict__ vpo) {
    size_t i = ((size_t)blockIdx.x * 256 + threadIdx.x) * 4;
    float4 a = *(const float4*)(part + i);
    float4 b = *(const float4*)(part + (size_t)4096 * 256 + i);
    a.x += b.x; a.y += b.y; a.z += b.z; a.w += b.w;
    *(float4*)(vpo + i) = a;
}

// ============================================================================
// fuse: out[bm] = relu((vp[b] ⊙ up[bm]) @ Wp16^T + bp)   128 x 256, K=256
// Single fp16 product. Wp fully smem-resident (4 chunk-tiles x 32KB).
// smem: B 128K | A 2x16K | mul 1K  = ~165KB
// ============================================================================
__global__ void __launch_bounds__(256) fuse_mma(
    const float* __restrict__ up, const float* __restrict__ vp,
    const __half* __restrict__ wp, const float* __restrict__ bp,
    float* __restrict__ out)
{
    extern __shared__ char dsm[];
    uint32_t sb_raw = smem_u32(dsm);
    uint32_t sb = (sb_raw + 1023u) & ~1023u;
    char* smp = dsm + (sb - sb_raw);

    constexpr uint32_t OFF_A = 131072, ABUF = 16384, OFF_MUL = 163840;

    const int bm = blockIdx.x, b = bm >> 5;
    const int tid = threadIdx.x;
    const int wid = tid >> 5, lane = tid & 31;
    const int wm = (wid >> 2) * 64, wn = (wid & 3) * 64;

    float* muls = (float*)(smp + OFF_MUL);
    muls[tid] = up[(size_t)bm * 256 + tid];

    // B: copy all of Wp16 into 4 swizzled chunk-tiles (row = n, 128B per chunk)
    {
        const __half* src = wp + (size_t)tid * 256;
#pragma unroll
        for (int kc = 0; kc < 4; kc++) {
            char* dstb = smp + kc * 32768;
#pragma unroll
            for (int j = 0; j < 8; j++)
                *(uint4*)(dstb + SWZ((uint32_t)(tid * 128 + j * 16))) =
                    *(const uint4*)(src + kc * 64 + j * 8);
        }
    }

    const int arow = tid >> 1, ahalf = tid & 1;
    const uint32_t arowoff = (uint32_t)(arow * 128 + ahalf * 64);
    const float* vbase = vp + (size_t)(b * 128 + arow) * 256 + ahalf * 32;
    const float* mbase = muls + ahalf * 32;

    float c[4][8][4];
#pragma unroll
    for (int i = 0; i < 4; i++)
#pragma unroll
        for (int j = 0; j < 8; j++)
#pragma unroll
            for (int q = 0; q < 4; q++) c[i][j][q] = 0.f;

    float4 xa[8];
    auto loadA = [&](int kc) {
#pragma unroll
        for (int i = 0; i < 8; i++) xa[i] = *(const float4*)(vbase + kc * 64 + i * 4);
    };
    auto storeA = [&](int kc, int bf) {
        char* p = smp + OFF_A + bf * ABUF;
        const float* mp = mbase + kc * 64;
#pragma unroll
        for (int i = 0; i < 8; i++) {
            const float4 m = *(const float4*)(mp + i * 4);
            __half h0 = __float2half_rn(xa[i].x * m.x), h1 = __float2half_rn(xa[i].y * m.y);
            __half h2 = __float2half_rn(xa[i].z * m.z), h3 = __float2half_rn(xa[i].w * m.w);
            *(uint2*)(p + SWZ(arowoff + i * 8)) = make_uint2(packh(h0, h1), packh(h2, h3));
        }
    };
    auto mmas = [&](int kc, int bf) {
        uint32_t abase = sb + OFF_A + bf * ABUF;
        uint32_t bbase = sb + kc * 32768;
#pragma unroll
        for (int ks = 0; ks < 4; ks++) {
            uint32_t af[4][4], bf2[8][2];
            const uint32_t acol = (uint32_t)(ks * 32 + (lane >> 4) * 16);
#pragma unroll
            for (int mi = 0; mi < 4; mi++) {
                uint32_t ro = (uint32_t)((wm + mi * 16 + (lane & 15)) * 128) + acol;
                ldsm4(af[mi][0], af[mi][1], af[mi][2], af[mi][3], abase + SWZ(ro));
            }
#pragma unroll
            for (int np = 0; np < 4; np++) {
                uint32_t ro = (uint32_t)((wn + np * 16 + (lane & 15)) * 128) + acol;
                uint32_t m0, m1, m2, m3;
                ldsm4(m0, m1, m2, m3, bbase + SWZ(ro));
                bf2[2 * np][0] = m0; bf2[2 * np][1] = m2;
                bf2[2 * np + 1][0] = m1; bf2[2 * np + 1][1] = m3;
            }
#pragma unroll
            for (int mi = 0; mi < 4; mi++)
#pragma unroll
                for (int nj = 0; nj < 8; nj++) mma_f16(c[mi][nj], af[mi], bf2[nj]);
        }
    };

    loadA(0);
    __syncthreads();          // muls (and B) visible
    storeA(0, 0);
    __syncthreads();          // A buf0 ready
    for (int kc = 0; kc < 4; kc++) {
        if (kc < 3) loadA(kc + 1);
        mmas(kc, kc & 1);
        if (kc < 3) storeA(kc + 1, (kc + 1) & 1);
        __syncthreads();
    }

    // ---- epilogue: +bias, relu, store ----
    const int rin = lane >> 2, cin = (lane & 3) * 2;
    float* obase = out + (size_t)bm * 128 * 256;
#pragma unroll
    for (int nj = 0; nj < 8; nj++) {
        const int f = wn + nj * 8 + cin;
        const float b0 = bp[f], b1 = bp[f + 1];
#pragma unroll
        for (int mi = 0; mi < 4; mi++) {
            float* p0 = obase + (size_t)(wm + mi * 16 + rin) * 256 + f;
            *(float2*)p0 = make_float2(fmaxf(c[mi][nj][0] + b0, 0.f),
                                       fmaxf(c[mi][nj][1] + b1, 0.f));
            *(float2*)(p0 + 8 * 256) = make_float2(fmaxf(c[mi][nj][2] + b0, 0.f),
                                                   fmaxf(c[mi][nj][3] + b1, 0.f));
        }
    }
}

// -------------------- host launch -------------------------------------------
extern "C" void kernel_launch(void* const* d_in, const int* in_sizes, int n_in,
                              void* d_out, int out_size) {
    const float* u  = (const float*)d_in[0];   // (32,32,1024)
    const float* v  = (const float*)d_in[1];   // (32,128,2048)
    const float* Wu = (const float*)d_in[2];   // (256,1024)
    const float* Wv = (const float*)d_in[3];   // (256,2048)
    const float* Wp = (const float*)d_in[4];   // (256,256)
    const float* bp = (const float*)d_in[5];   // (256,)
    float* out = (float*)d_out;                // (32,32,128,256)

    float *up_p, *vp_p, *vpp_p;
    __half *wu, *wv, *wp;
    cudaGetSymbolAddress((void**)&up_p, g_up);
    cudaGetSymbolAddress((void**)&vp_p, g_vp);
    cudaGetSymbolAddress((void**)&vpp_p, g_vp_part);
    cudaGetSymbolAddress((void**)&wu, g_wu16);
    cudaGetSymbolAddress((void**)&wv, g_wv16);
    cudaGetSymbolAddress((void**)&wp, g_wp16);

    const int PROJ_SMEM = 2 * 49152 + 1024;      // 99328
    const int FUSE_SMEM = 163840 + 1024 + 1024;  // 165888
    cudaFuncSetAttribute(proj_mma, cudaFuncAttributeMaxDynamicSharedMemorySize, PROJ_SMEM);
    cudaFuncSetAttribute(fuse_mma, cudaFuncAttributeMaxDynamicSharedMemorySize, FUSE_SMEM);

    const int total = 256 * 1024 + 256 * 2048 + 256 * 256;
    prep_cvt<<<(total + 255) / 256, 256>>>(Wu, Wv, Wp, wu, wv, wp);
    proj_mma<<<144, 256, PROJ_SMEM>>>(u, v, wu, wv, up_p, vpp_p);
    vp_add<<<1024, 256>>>(vpp_p, vp_p);
    fuse_mma<<<1024, 256, FUSE_SMEM>>>(up_p, vp_p, wp, bp, out);
}

// round 7
// speedup vs baseline: 3.6512x; 1.3269x over previous
#include <cuda_runtime.h>
#include <cuda_fp16.h>
#include <cstdint>

// ============================================================================
// LowRankBilinearFusion, HMMA fp16, feed via cp.async, 2 CTAs/SM:
//   prep: u,v -> fp16 hi/lo (error-free split); Wu,Wv,Wp -> fp16
//   proj: up = u@Wu^T (fp32 out), vp_part = v@Wv^T k-split (fp32)
//   vp_add: vp16 = fp16(part0+part1)
//   fuse: out[bm,n0] = relu((vp16[b] ⊙h2 up16[bm]) @ Wp16^T + bp), N=128/CTA
// ============================================================================

__device__ float  g_up[1024 * 256];
__device__ float  g_vp_part[2 * 4096 * 256];
__device__ __half g_vp16[4096 * 256];
__device__ __half g_uh[1024 * 1024], g_ul[1024 * 1024];
__device__ __half g_vh[4096 * 2048], g_vl[4096 * 2048];
__device__ __half g_wu16[256 * 1024];
__device__ __half g_wv16[256 * 2048];
__device__ __half g_wp16[256 * 256];

#define SWZ(o) ((o) ^ (((o) >> 3) & 0x70))

__device__ __forceinline__ uint32_t smem_u32(const void* p) {
    uint32_t a;
    asm("{ .reg .u64 t; cvta.to.shared.u64 t, %1; cvt.u32.u64 %0, t; }" : "=r"(a) : "l"(p));
    return a;
}
__device__ __forceinline__ void ldsm4(uint32_t& r0, uint32_t& r1, uint32_t& r2, uint32_t& r3,
                                      uint32_t addr) {
    asm volatile("ldmatrix.sync.aligned.m8n8.x4.shared.b16 {%0,%1,%2,%3}, [%4];"
                 : "=r"(r0), "=r"(r1), "=r"(r2), "=r"(r3) : "r"(addr));
}
__device__ __forceinline__ void mma_f16(float* c, const uint32_t* a, const uint32_t* b) {
    asm volatile(
        "mma.sync.aligned.m16n8k16.row.col.f32.f16.f16.f32 "
        "{%0,%1,%2,%3}, {%4,%5,%6,%7}, {%8,%9}, {%0,%1,%2,%3};"
        : "+f"(c[0]), "+f"(c[1]), "+f"(c[2]), "+f"(c[3])
        : "r"(a[0]), "r"(a[1]), "r"(a[2]), "r"(a[3]), "r"(b[0]), "r"(b[1]));
}
__device__ __forceinline__ void cp16(uint32_t dst, const void* src) {
    asm volatile("cp.async.cg.shared.global [%0], [%1], 16;" :: "r"(dst), "l"(src));
}
__device__ __forceinline__ void cp_commit() { asm volatile("cp.async.commit_group;" ::: "memory"); }
template <int N>
__device__ __forceinline__ void cp_wait() { asm volatile("cp.async.wait_group %0;" :: "n"(N) : "memory"); }

// -------------------- prep: split inputs, convert weights --------------------
__global__ void __launch_bounds__(256) prep_cvt(
    const float* __restrict__ u, const float* __restrict__ v,
    const float* __restrict__ Wu, const float* __restrict__ Wv, const float* __restrict__ Wp,
    __half* uh, __half* ul, __half* vh, __half* vl,
    __half* wu, __half* wv, __half* wp)
{
    const int N1 = 1024 * 1024, N2 = 4096 * 2048;
    const int N3 = 256 * 1024, N4 = 256 * 2048, N5 = 256 * 256;
    int i = blockIdx.x * 256 + threadIdx.x;
    if (i < N1) {
        float x = u[i];
        __half h = __float2half_rn(x);
        uh[i] = h; ul[i] = __float2half_rn(x - __half2float(h));
    } else if (i < N1 + N2) {
        int j = i - N1;
        float x = v[j];
        __half h = __float2half_rn(x);
        vh[j] = h; vl[j] = __float2half_rn(x - __half2float(h));
    } else if (i < N1 + N2 + N3) {
        int j = i - N1 - N2; wu[j] = __float2half_rn(Wu[j]);
    } else if (i < N1 + N2 + N3 + N4) {
        int j = i - N1 - N2 - N3; wv[j] = __float2half_rn(Wv[j]);
    } else if (i < N1 + N2 + N3 + N4 + N5) {
        int j = i - N1 - N2 - N3 - N4; wp[j] = __float2half_rn(Wp[j]);
    }
}

// ============================================================================
// proj: C[128x128] = (Ah+Al) @ B16^T, K = 1024 per CTA (16 chunks of 64).
// Feed entirely cp.async (pre-split fp16 inputs). smem: 2 x {AH16K|AL16K|B16K}.
// Grid: 0..15 up (mt x n0), 16..143 vp (mt x n0 x kh).
// ============================================================================
__global__ void __launch_bounds__(256, 2) proj_mma(
    const __half* __restrict__ uh, const __half* __restrict__ ul,
    const __half* __restrict__ vh, const __half* __restrict__ vl,
    const __half* __restrict__ wu, const __half* __restrict__ wv,
    float* __restrict__ up, float* __restrict__ vp_part)
{
    extern __shared__ char dsm[];
    uint32_t sb_raw = smem_u32(dsm);
    uint32_t sb = (sb_raw + 1023u) & ~1023u;

    constexpr uint32_t BUF = 49152, OFF_AL = 16384, OFF_B = 32768;

    const int bid = blockIdx.x;
    const int tid = threadIdx.x;
    const int wid = tid >> 5, lane = tid & 31;
    const int wm = (wid >> 2) * 64, wn = (wid & 3) * 32;

    const __half *Ah, *Al, *B; float* C;
    int lda, ldb;
    if (bid < 16) {
        int mt = bid >> 1, n0 = bid & 1;
        Ah = uh + (size_t)mt * 128 * 1024; Al = ul + (size_t)mt * 128 * 1024; lda = 1024;
        B = wu + (size_t)n0 * 128 * 1024; ldb = 1024;
        C = up + (size_t)mt * 128 * 256 + n0 * 128;
    } else {
        int b2 = bid - 16;
        int mt = b2 >> 2, n0 = (b2 >> 1) & 1, kh = b2 & 1;
        Ah = vh + (size_t)mt * 128 * 2048 + kh * 1024;
        Al = vl + (size_t)mt * 128 * 2048 + kh * 1024; lda = 2048;
        B = wv + (size_t)n0 * 128 * 2048 + kh * 1024; ldb = 2048;
        C = vp_part + (size_t)kh * 4096 * 256 + (size_t)mt * 128 * 256 + n0 * 128;
    }

    const int row = tid >> 1, seg = tid & 1;
    const __half* pAh = Ah + (size_t)row * lda + seg * 32;
    const __half* pAl = Al + (size_t)row * lda + seg * 32;
    const __half* pB  = B  + (size_t)row * ldb + seg * 32;
    const uint32_t rowoff = (uint32_t)(row * 128 + seg * 64);

    float c[4][4][4];
#pragma unroll
    for (int i = 0; i < 4; i++)
#pragma unroll
        for (int j = 0; j < 4; j++)
#pragma unroll
            for (int q = 0; q < 4; q++) c[i][j][q] = 0.f;

    auto issue = [&](int kc, int bf) {
        uint32_t base = sb + (uint32_t)bf * BUF;
#pragma unroll
        for (int j = 0; j < 4; j++) {
            uint32_t sw = SWZ(rowoff + j * 16);
            cp16(base + sw,          pAh + kc * 64 + j * 8);
            cp16(base + OFF_AL + sw, pAl + kc * 64 + j * 8);
            cp16(base + OFF_B + sw,  pB  + kc * 64 + j * 8);
        }
    };
    auto mmas = [&](int bf) {
        uint32_t base = sb + (uint32_t)bf * BUF;
#pragma unroll
        for (int ks = 0; ks < 4; ks++) {
            uint32_t ah[4][4], al[4][4], bh[4][2];
            const uint32_t acol = (uint32_t)(ks * 32 + (lane >> 4) * 16);
#pragma unroll
            for (int mi = 0; mi < 4; mi++) {
                uint32_t ro = (uint32_t)((wm + mi * 16 + (lane & 15)) * 128) + acol;
                ldsm4(ah[mi][0], ah[mi][1], ah[mi][2], ah[mi][3], base + SWZ(ro));
                ldsm4(al[mi][0], al[mi][1], al[mi][2], al[mi][3], base + OFF_AL + SWZ(ro));
            }
#pragma unroll
            for (int np = 0; np < 2; np++) {
                uint32_t ro = (uint32_t)((wn + np * 16 + (lane & 15)) * 128) + acol;
                uint32_t m0, m1, m2, m3;
                ldsm4(m0, m1, m2, m3, base + OFF_B + SWZ(ro));
                bh[2 * np][0] = m0; bh[2 * np][1] = m2;
                bh[2 * np + 1][0] = m1; bh[2 * np + 1][1] = m3;
            }
#pragma unroll
            for (int mi = 0; mi < 4; mi++)
#pragma unroll
                for (int nj = 0; nj < 4; nj++) {
                    mma_f16(c[mi][nj], ah[mi], bh[nj]);
                    mma_f16(c[mi][nj], al[mi], bh[nj]);
                }
        }
    };

    issue(0, 0); cp_commit();
    for (int kc = 0; kc < 16; kc++) {
        if (kc < 15) { issue(kc + 1, (kc + 1) & 1); cp_commit(); cp_wait<1>(); }
        else cp_wait<0>();
        __syncthreads();
        mmas(kc & 1);
        __syncthreads();
    }

    const int rin = lane >> 2, cin = (lane & 3) * 2;
#pragma unroll
    for (int mi = 0; mi < 4; mi++)
#pragma unroll
        for (int nj = 0; nj < 4; nj++) {
            float* p0 = C + (size_t)(wm + mi * 16 + rin) * 256 + wn + nj * 8 + cin;
            *(float2*)p0 = make_float2(c[mi][nj][0], c[mi][nj][1]);
            *(float2*)(p0 + 8 * 256) = make_float2(c[mi][nj][2], c[mi][nj][3]);
        }
}

// -------------------- vp16 = fp16(part0 + part1) -----------------------------
__global__ void __launch_bounds__(256) vp_add(const float* __restrict__ part,
                                              __half* __restrict__ vpo) {
    size_t i = ((size_t)blockIdx.x * 256 + threadIdx.x) * 4;
    float4 a = *(const float4*)(part + i);
    float4 b = *(const float4*)(part + (size_t)4096 * 256 + i);
    __half2 h0 = __floats2half2_rn(a.x + b.x, a.y + b.y);
    __half2 h1 = __floats2half2_rn(a.z + b.z, a.w + b.w);
    uint2 o;
    o.x = *(uint32_t*)&h0; o.y = *(uint32_t*)&h1;
    *(uint2*)(vpo + i) = o;
}

// ============================================================================
// fuse: out[bm, n0] = relu((vp16[b] ⊙ up16[bm]) @ Wp16[n0]^T + bp)
// 128 x 128 per CTA, K=256. A built once (smem-resident, 4 x 16KB chunks),
// B double-buffered via cp.async. smem ~98.8KB -> 2 CTAs/SM.
// ============================================================================
__global__ void __launch_bounds__(256, 2) fuse_mma(
    const float* __restrict__ up, const __half* __restrict__ vp16,
    const __half* __restrict__ wp, const float* __restrict__ bp,
    float* __restrict__ out)
{
    extern __shared__ char dsm[];
    uint32_t sb_raw = smem_u32(dsm);
    uint32_t sb = (sb_raw + 1023u) & ~1023u;
    char* smp = dsm + (sb - sb_raw);

    constexpr uint32_t OFF_B = 65536, BBUF = 16384, OFF_UPS = 98304;

    const int bm = blockIdx.x, b = bm >> 5;
    const int n0 = blockIdx.y;
    const int tid = threadIdx.x;
    const int wid = tid >> 5, lane = tid & 31;
    const int wm = (wid >> 2) * 64, wn = (wid & 3) * 32;

    // up[bm] -> half2 multipliers in smem
    __half2* ups2 = (__half2*)(smp + OFF_UPS);
    if (tid < 128) {
        float2 f = *(const float2*)(up + (size_t)bm * 256 + 2 * tid);
        ups2[tid] = __floats2half2_rn(f.x, f.y);
    }

    const int row = tid >> 1, seg = tid & 1;
    const __half* pB = wp + (size_t)(n0 * 128 + row) * 256 + seg * 32;
    const uint32_t rowoff = (uint32_t)(row * 128 + seg * 64);

    // B chunk 0 in flight early
#pragma unroll
    for (int j = 0; j < 4; j++)
        cp16(sb + OFF_B + SWZ(rowoff + j * 16), pB + j * 8);
    cp_commit();

    __syncthreads();   // ups2 visible

    // Build A resident: A[r, k] = vp16[b*128+r, k] * up16[bm, k]
    {
        const __half* vrow = vp16 + (size_t)(b * 128 + row) * 256 + seg * 32;
#pragma unroll
        for (int kc = 0; kc < 4; kc++) {
            char* dstc = smp + kc * BBUF;
#pragma unroll
            for (int j = 0; j < 4; j++) {
                uint4 x = *(const uint4*)(vrow + kc * 64 + j * 8);
                const __half2* m = &ups2[kc * 32 + seg * 16 + j * 4];
                *(__half2*)&x.x = __hmul2(*(__half2*)&x.x, m[0]);
                *(__half2*)&x.y = __hmul2(*(__half2*)&x.y, m[1]);
                *(__half2*)&x.z = __hmul2(*(__half2*)&x.z, m[2]);
                *(__half2*)&x.w = __hmul2(*(__half2*)&x.w, m[3]);
                *(uint4*)(dstc + SWZ(rowoff + j * 16)) = x;
            }
        }
    }

    float c[4][4][4];
#pragma unroll
    for (int i = 0; i < 4; i++)
#pragma unroll
        for (int j = 0; j < 4; j++)
#pragma unroll
            for (int q = 0; q < 4; q++) c[i][j][q] = 0.f;

    for (int kc = 0; kc < 4; kc++) {
        if (kc < 3) {
            uint32_t bbase = sb + OFF_B + (uint32_t)((kc + 1) & 1) * BBUF;
#pragma unroll
            for (int j = 0; j < 4; j++)
                cp16(bbase + SWZ(rowoff + j * 16), pB + (kc + 1) * 64 + j * 8);
            cp_commit();
            cp_wait<1>();
        } else {
            cp_wait<0>();
        }
        __syncthreads();

        uint32_t abase = sb + (uint32_t)kc * BBUF;
        uint32_t bbase = sb + OFF_B + (uint32_t)(kc & 1) * BBUF;
#pragma unroll
        for (int ks = 0; ks < 4; ks++) {
            uint32_t af[4][4], bf[4][2];
            const uint32_t acol = (uint32_t)(ks * 32 + (lane >> 4) * 16);
#pragma unroll
            for (int mi = 0; mi < 4; mi++) {
                uint32_t ro = (uint32_t)((wm + mi * 16 + (lane & 15)) * 128) + acol;
                ldsm4(af[mi][0], af[mi][1], af[mi][2], af[mi][3], abase + SWZ(ro));
            }
#pragma unroll
            for (int np = 0; np < 2; np++) {
                uint32_t ro = (uint32_t)((wn + np * 16 + (lane & 15)) * 128) + acol;
                uint32_t m0, m1, m2, m3;
                ldsm4(m0, m1, m2, m3, bbase + SWZ(ro));
                bf[2 * np][0] = m0; bf[2 * np][1] = m2;
                bf[2 * np + 1][0] = m1; bf[2 * np + 1][1] = m3;
            }
#pragma unroll
            for (int mi = 0; mi < 4; mi++)
#pragma unroll
                for (int nj = 0; nj < 4; nj++)
                    mma_f16(c[mi][nj], af[mi], bf[nj]);
        }
        __syncthreads();
    }

    // epilogue: +bias, relu, store
    const int rin = lane >> 2, cin = (lane & 3) * 2;
    float* obase = out + (size_t)bm * 128 * 256 + n0 * 128;
#pragma unroll
    for (int nj = 0; nj < 4; nj++) {
        const int f = wn + nj * 8 + cin;
        const float b0 = bp[n0 * 128 + f], b1 = bp[n0 * 128 + f + 1];
#pragma unroll
        for (int mi = 0; mi < 4; mi++) {
            float* p0 = obase + (size_t)(wm + mi * 16 + rin) * 256 + f;
            *(float2*)p0 = make_float2(fmaxf(c[mi][nj][0] + b0, 0.f),
                                       fmaxf(c[mi][nj][1] + b1, 0.f));
            *(float2*)(p0 + 8 * 256) = make_float2(fmaxf(c[mi][nj][2] + b0, 0.f),
                                                   fmaxf(c[mi][nj][3] + b1, 0.f));
        }
    }
}

// -------------------- host launch -------------------------------------------
extern "C" void kernel_launch(void* const* d_in, const int* in_sizes, int n_in,
                              void* d_out, int out_size) {
    const float* u  = (const float*)d_in[0];   // (32,32,1024)
    const float* v  = (const float*)d_in[1];   // (32,128,2048)
    const float* Wu = (const float*)d_in[2];   // (256,1024)
    const float* Wv = (const float*)d_in[3];   // (256,2048)
    const float* Wp = (const float*)d_in[4];   // (256,256)
    const float* bp = (const float*)d_in[5];   // (256,)
    float* out = (float*)d_out;                // (32,32,128,256)

    float *up_p, *vpp_p;
    __half *vp16, *uh, *ul, *vh, *vl, *wu, *wv, *wp;
    cudaGetSymbolAddress((void**)&up_p, g_up);
    cudaGetSymbolAddress((void**)&vpp_p, g_vp_part);
    cudaGetSymbolAddress((void**)&vp16, g_vp16);
    cudaGetSymbolAddress((void**)&uh, g_uh);
    cudaGetSymbolAddress((void**)&ul, g_ul);
    cudaGetSymbolAddress((void**)&vh, g_vh);
    cudaGetSymbolAddress((void**)&vl, g_vl);
    cudaGetSymbolAddress((void**)&wu, g_wu16);
    cudaGetSymbolAddress((void**)&wv, g_wv16);
    cudaGetSymbolAddress((void**)&wp, g_wp16);

    const int PROJ_SMEM = 2 * 49152 + 1024;          // 99328
    const int FUSE_SMEM = 98304 + 512 + 1024;        // 99840
    cudaFuncSetAttribute(proj_mma, cudaFuncAttributeMaxDynamicSharedMemorySize, PROJ_SMEM);
    cudaFuncSetAttribute(fuse_mma, cudaFuncAttributeMaxDynamicSharedMemorySize, FUSE_SMEM);

    const int total = 1024 * 1024 + 4096 * 2048 + 256 * 1024 + 256 * 2048 + 256 * 256;
    prep_cvt<<<(total + 255) / 256, 256>>>(u, v, Wu, Wv, Wp, uh, ul, vh, vl, wu, wv, wp);
    proj_mma<<<144, 256, PROJ_SMEM>>>(uh, ul, vh, vl, wu, wv, up_p, vpp_p);
    vp_add<<<1024, 256>>>(vpp_p, vp16);
    fuse_mma<<<dim3(1024, 2), 256, FUSE_SMEM>>>(up_p, vp16, wp, bp, out);
}